// round 1
// baseline (speedup 1.0000x reference)
#include <cuda_runtime.h>
#include <math.h>

#define S_     2048
#define E_     2048
#define NH     32
#define NG     8
#define DH     64
#define QKV_N  3072   /* (H + 2G) * D */
#define SW_    128

// Scratch (allocation-free rule: __device__ globals)
__device__ float g_qkv[(size_t)S_ * QKV_N];   // 25.2 MB
__device__ float g_ctx[(size_t)S_ * E_];      // 16.8 MB

// ---------------------------------------------------------------------------
// SGEMM: C[M,N] = A[M,K] * B[N,K]^T + bias[N]
// 128x128 block tile, BK=8, 256 threads, 8x8 per-thread micro-tile.
// M,N divisible by 128; K divisible by 8 (true for all uses here).
// ---------------------------------------------------------------------------
__global__ __launch_bounds__(256, 2)
void sgemm_nt(int M, int N, int K,
              const float* __restrict__ A,
              const float* __restrict__ B,
              const float* __restrict__ bias,
              float* __restrict__ C)
{
    __shared__ float As[8][128];
    __shared__ float Bs[8][128];

    const int tid = threadIdx.x;
    const int bm  = blockIdx.y * 128;
    const int bn  = blockIdx.x * 128;
    const int tx  = tid & 15;         // 0..15 -> N
    const int ty  = tid >> 4;         // 0..15 -> M
    const int lrow = tid >> 1;        // 0..127
    const int lcol = (tid & 1) << 2;  // 0 or 4

    const float* Ap = A + (size_t)(bm + lrow) * K + lcol;
    const float* Bp = B + (size_t)(bn + lrow) * K + lcol;

    float c[8][8];
    #pragma unroll
    for (int i = 0; i < 8; i++)
        #pragma unroll
        for (int j = 0; j < 8; j++) c[i][j] = 0.f;

    for (int k0 = 0; k0 < K; k0 += 8) {
        float4 av = *(const float4*)(Ap + k0);
        float4 bv = *(const float4*)(Bp + k0);
        As[lcol + 0][lrow] = av.x; As[lcol + 1][lrow] = av.y;
        As[lcol + 2][lrow] = av.z; As[lcol + 3][lrow] = av.w;
        Bs[lcol + 0][lrow] = bv.x; Bs[lcol + 1][lrow] = bv.y;
        Bs[lcol + 2][lrow] = bv.z; Bs[lcol + 3][lrow] = bv.w;
        __syncthreads();

        #pragma unroll
        for (int kk = 0; kk < 8; kk++) {
            float4 a0 = *(const float4*)&As[kk][ty * 4];
            float4 a1 = *(const float4*)&As[kk][64 + ty * 4];
            float4 b0 = *(const float4*)&Bs[kk][tx * 4];
            float4 b1 = *(const float4*)&Bs[kk][64 + tx * 4];
            float a[8] = {a0.x, a0.y, a0.z, a0.w, a1.x, a1.y, a1.z, a1.w};
            float b[8] = {b0.x, b0.y, b0.z, b0.w, b1.x, b1.y, b1.z, b1.w};
            #pragma unroll
            for (int i = 0; i < 8; i++)
                #pragma unroll
                for (int j = 0; j < 8; j++)
                    c[i][j] += a[i] * b[j];
        }
        __syncthreads();
    }

    float bb[8];
    #pragma unroll
    for (int j = 0; j < 8; j++) {
        int n = bn + ((j < 4) ? (tx * 4 + j) : (64 + tx * 4 + (j - 4)));
        bb[j] = bias[n];
    }
    #pragma unroll
    for (int i = 0; i < 8; i++) {
        int m = bm + ((i < 4) ? (ty * 4 + i) : (64 + ty * 4 + (i - 4)));
        float* cp = C + (size_t)m * N + bn;
        float4 v0 = make_float4(c[i][0] + bb[0], c[i][1] + bb[1],
                                c[i][2] + bb[2], c[i][3] + bb[3]);
        float4 v1 = make_float4(c[i][4] + bb[4], c[i][5] + bb[5],
                                c[i][6] + bb[6], c[i][7] + bb[7]);
        *(float4*)(cp + tx * 4)      = v0;
        *(float4*)(cp + 64 + tx * 4) = v1;
    }
}

// ---------------------------------------------------------------------------
// YaRN RoPE in-place on Q (heads 0..31) and K (heads 32..39) in g_qkv.
// grid (S, 40), 32 threads; thread k handles the (k, k+32) pair.
// ---------------------------------------------------------------------------
__global__ void rope_kernel(const int* __restrict__ pos_ids)
{
    const int i  = blockIdx.x;   // position
    const int hh = blockIdx.y;   // head 0..39
    const int k  = threadIdx.x;  // 0..31

    float freq = powf(10000.0f, -((float)(2 * k) / 64.0f));
    float wl   = 6.283185307179586f / freq;
    float t    = (wl - 128.0f) / (4096.0f - 128.0f);
    t = fminf(fmaxf(t, 0.0f), 1.0f);
    float eff  = freq * (1.0f - t) + (freq * 0.5f) * t;
    float conc = 0.1f * logf(2.0f) + 1.0f;
    float ang  = (float)pos_ids[i] * eff * conc;
    float sv = sinf(ang), cv = cosf(ang);

    float* p = g_qkv + (size_t)i * QKV_N + hh * DH;
    float x1 = p[k], x2 = p[k + 32];
    p[k]      = x1 * cv - x2 * sv;
    p[k + 32] = x2 * cv + x1 * sv;
}

// ---------------------------------------------------------------------------
// Windowed attention with sink. One block = one (query i, q-head h).
// Valid keys: j in [max(0, i-127), i]  (<=128 keys).
// ---------------------------------------------------------------------------
__global__ __launch_bounds__(128)
void attn_kernel(const float* __restrict__ sinks)
{
    const int i   = blockIdx.x;
    const int h   = blockIdx.y;
    const int g   = h >> 2;            // GS = 4
    const int tid = threadIdx.x;

    __shared__ float qs[64];
    __shared__ float Ks[128 * 65];     // padded stride 65: conflict-free
    __shared__ float ps[128];
    __shared__ float red[128];
    __shared__ float cpart[128];

    const int jstart = max(0, i - (SW_ - 1));
    const int nk     = i - jstart + 1;

    if (tid < 64) qs[tid] = g_qkv[(size_t)i * QKV_N + h * DH + tid];

    const int kofs = (NH + g) * DH;
    for (int e = tid; e < nk * 64; e += 128) {
        int j = e >> 6, d = e & 63;
        Ks[j * 65 + d] = g_qkv[(size_t)(jstart + j) * QKV_N + kofs + d];
    }
    __syncthreads();

    float s = -INFINITY;
    if (tid < nk) {
        float acc = 0.f;
        #pragma unroll
        for (int d = 0; d < 64; d++) acc += qs[d] * Ks[tid * 65 + d];
        s = acc * 0.125f;   // 1/sqrt(64)
    }

    // block max
    red[tid] = s;
    __syncthreads();
    #pragma unroll
    for (int off = 64; off > 0; off >>= 1) {
        if (tid < off) red[tid] = fmaxf(red[tid], red[tid + off]);
        __syncthreads();
    }
    const float sink = sinks[h];
    const float m = fmaxf(red[0], sink);
    __syncthreads();

    float p = (tid < nk) ? expf(s - m) : 0.f;
    ps[tid] = p;
    red[tid] = p;
    __syncthreads();
    #pragma unroll
    for (int off = 64; off > 0; off >>= 1) {
        if (tid < off) red[tid] += red[tid + off];
        __syncthreads();
    }
    const float inv = 1.f / (red[0] + expf(sink - m));
    __syncthreads();

    // stage V (reuse Ks)
    const int vofs = (NH + NG + g) * DH;
    for (int e = tid; e < nk * 64; e += 128) {
        int j = e >> 6, d = e & 63;
        Ks[j * 65 + d] = g_qkv[(size_t)(jstart + j) * QKV_N + vofs + d];
    }
    __syncthreads();

    const int d    = tid & 63;
    const int half = tid >> 6;
    float acc = 0.f;
    for (int j = half; j < nk; j += 2) acc += ps[j] * Ks[j * 65 + d];
    cpart[tid] = acc;
    __syncthreads();
    if (tid < 64)
        g_ctx[(size_t)i * E_ + h * DH + d] = (cpart[d] + cpart[64 + d]) * inv;
}

// ---------------------------------------------------------------------------
extern "C" void kernel_launch(void* const* d_in, const int* in_sizes, int n_in,
                              void* d_out, int out_size)
{
    const float* x     = (const float*)d_in[0];
    const int*   pos   = (const int*)  d_in[1];
    /* d_in[2] attn_mask: causal mask, reproduced analytically */
    const float* Wqkv  = (const float*)d_in[3];
    const float* bqkv  = (const float*)d_in[4];
    const float* Wout  = (const float*)d_in[5];
    const float* bout  = (const float*)d_in[6];
    const float* sinks = (const float*)d_in[7];
    float* out = (float*)d_out;

    float *qkv_p = nullptr, *ctx_p = nullptr;
    cudaGetSymbolAddress((void**)&qkv_p, g_qkv);
    cudaGetSymbolAddress((void**)&ctx_p, g_ctx);

    // 1) qkv = x @ Wqkv^T + bqkv
    dim3 g1(QKV_N / 128, S_ / 128);
    sgemm_nt<<<g1, 256>>>(S_, QKV_N, E_, x, Wqkv, bqkv, qkv_p);

    // 2) RoPE (Q + K heads, in place)
    rope_kernel<<<dim3(S_, NH + NG), 32>>>(pos);

    // 3) windowed sink attention -> g_ctx
    attn_kernel<<<dim3(S_, NH), 128>>>(sinks);

    // 4) out = ctx @ Wout^T + bout
    dim3 g2(E_ / 128, S_ / 128);
    sgemm_nt<<<g2, 256>>>(S_, E_, E_, ctx_p, Wout, bout, out);
}

// round 3
// speedup vs baseline: 2.3574x; 2.3574x over previous
#include <cuda_runtime.h>
#include <cuda_bf16.h>
#include <math.h>
#include <stdint.h>

#define S_     2048
#define E_     2048
#define NH     32
#define NG     8
#define DH     64
#define QKV_N  3072   /* (H + 2G) * D */
#define SW_    128

// ---------------- scratch (__device__ globals; no allocs allowed) ----------
__device__ float g_qkv[(size_t)S_ * QKV_N];
__device__ float g_ctx[(size_t)S_ * E_];
__device__ __nv_bfloat16 g_xhi[(size_t)S_ * E_],     g_xlo[(size_t)S_ * E_];
__device__ __nv_bfloat16 g_wqhi[(size_t)QKV_N * E_], g_wqlo[(size_t)QKV_N * E_];
__device__ __nv_bfloat16 g_wohi[(size_t)E_ * E_],    g_wolo[(size_t)E_ * E_];
__device__ __nv_bfloat16 g_chi[(size_t)S_ * E_],     g_clo[(size_t)S_ * E_];

// ---------------- helpers --------------------------------------------------
__device__ __forceinline__ uint32_t smem_u32(const void* p) {
    return (uint32_t)__cvta_generic_to_shared(p);
}
__device__ __forceinline__ void cp16(uint32_t dst, const void* src) {
    asm volatile("cp.async.cg.shared.global [%0], [%1], 16;"
                 :: "r"(dst), "l"(src) : "memory");
}
__device__ __forceinline__ void ldm_x4(uint32_t* r, uint32_t addr) {
    asm volatile("ldmatrix.sync.aligned.m8n8.x4.shared.b16 {%0,%1,%2,%3}, [%4];"
                 : "=r"(r[0]), "=r"(r[1]), "=r"(r[2]), "=r"(r[3]) : "r"(addr));
}
__device__ __forceinline__ void mma_bf16(float* c, const uint32_t* a,
                                         uint32_t b0, uint32_t b1) {
    asm volatile(
        "mma.sync.aligned.m16n8k16.row.col.f32.bf16.bf16.f32 "
        "{%0,%1,%2,%3},{%4,%5,%6,%7},{%8,%9},{%0,%1,%2,%3};"
        : "+f"(c[0]), "+f"(c[1]), "+f"(c[2]), "+f"(c[3])
        : "r"(a[0]), "r"(a[1]), "r"(a[2]), "r"(a[3]), "r"(b0), "r"(b1));
}

// ---------------- fp32 -> (hi, lo) bf16 split ------------------------------
__global__ __launch_bounds__(256)
void conv_hilo(const float* __restrict__ src,
               __nv_bfloat16* __restrict__ hi,
               __nv_bfloat16* __restrict__ lo, int n4)
{
    int i = blockIdx.x * 256 + threadIdx.x;
    if (i >= n4) return;
    float4 v = ((const float4*)src)[i];
    float f[4] = {v.x, v.y, v.z, v.w};
    __nv_bfloat16 h[4], l[4];
    #pragma unroll
    for (int k = 0; k < 4; k++) {
        h[k] = __float2bfloat16(f[k]);
        l[k] = __float2bfloat16(f[k] - __bfloat162float(h[k]));
    }
    __nv_bfloat162* hp = (__nv_bfloat162*)hi;
    __nv_bfloat162* lp = (__nv_bfloat162*)lo;
    hp[2*i]   = __nv_bfloat162(h[0], h[1]);
    hp[2*i+1] = __nv_bfloat162(h[2], h[3]);
    lp[2*i]   = __nv_bfloat162(l[0], l[1]);
    lp[2*i+1] = __nv_bfloat162(l[2], l[3]);
}

// ---------------------------------------------------------------------------
// HMMA split-bf16 GEMM: C[M,N] = Ahi/lo[M,K] * (Bhi/lo[N,K])^T + bias[N]
// 128x128 CTA, BK=32, 4-stage cp.async pipeline, 8 warps (2x4), 64x32/warp.
// smem per stage: 4 tiles (Ahi,Alo,Bhi,Blo) x 128 rows x 64B = 32KB.
// Swizzle: 16B slot s at row r lands at 16*(s ^ ((r>>1)&3)) -> ldmatrix
// conflict-free.
// ---------------------------------------------------------------------------
#define STAGES     4
#define STAGE_B    32768
#define GEMM_SMEM  (STAGES * STAGE_B)

__global__ __launch_bounds__(256, 1)
void gemm_mma(int M, int N, int K,
              const __nv_bfloat16* __restrict__ Ahi,
              const __nv_bfloat16* __restrict__ Alo,
              const __nv_bfloat16* __restrict__ Bhi,
              const __nv_bfloat16* __restrict__ Blo,
              const float* __restrict__ bias,
              float* __restrict__ C)
{
    extern __shared__ char smem[];
    const uint32_t sbase = smem_u32(smem);
    const int tid  = threadIdx.x;
    const int wid  = tid >> 5, lane = tid & 31;
    const int bm   = blockIdx.y * 128, bn = blockIdx.x * 128;
    const int mi   = (wid >> 2) * 64;   // warp m offset
    const int ni   = (wid & 3) * 32;    // warp n offset
    const int NC   = K >> 5;            // chunks of 32

    auto load_chunk = [&](int kc, int st) {
        const __nv_bfloat16* srcs[4] = {Ahi, Alo, Bhi, Blo};
        const int r0s[4] = {bm, bm, bn, bn};
        uint32_t stb = sbase + st * STAGE_B;
        #pragma unroll
        for (int t4 = 0; t4 < 4; t4++) {
            #pragma unroll
            for (int rep = 0; rep < 2; rep++) {
                int idx  = tid + rep * 256;
                int r    = idx >> 2, slot = idx & 3;
                const void* src = srcs[t4] + (size_t)(r0s[t4] + r) * K + kc * 32 + slot * 8;
                uint32_t dst = stb + t4 * 8192 + r * 64 + 16 * (slot ^ ((r >> 1) & 3));
                cp16(dst, src);
            }
        }
        asm volatile("cp.async.commit_group;" ::: "memory");
    };

    float acc[4][4][4];
    #pragma unroll
    for (int i2 = 0; i2 < 4; i2++)
        #pragma unroll
        for (int j = 0; j < 4; j++)
            #pragma unroll
            for (int q = 0; q < 4; q++) acc[i2][j][q] = 0.f;

    load_chunk(0, 0);
    load_chunk(1, 1);
    load_chunk(2, 2);

    for (int c = 0; c < NC; ++c) {
        asm volatile("cp.async.wait_group 2;" ::: "memory");
        __syncthreads();
        if (c + 3 < NC) load_chunk(c + 3, (c + 3) & 3);
        else asm volatile("cp.async.commit_group;" ::: "memory");

        uint32_t stb = sbase + (c & 3) * STAGE_B;
        #pragma unroll
        for (int ks = 0; ks < 2; ks++) {
            uint32_t ah[4][4], al[4][4];
            #pragma unroll
            for (int i2 = 0; i2 < 4; i2++) {
                int r    = mi + i2 * 16 + (lane & 15);
                int slot = ks * 2 + (lane >> 4);
                uint32_t off = (uint32_t)(r * 64 + 16 * (slot ^ ((r >> 1) & 3)));
                ldm_x4(ah[i2], stb + 0    + off);
                ldm_x4(al[i2], stb + 8192 + off);
            }
            uint32_t bh[2][4], bl[2][4];
            #pragma unroll
            for (int jp = 0; jp < 2; jp++) {
                int r    = ni + jp * 16 + (lane & 15);
                int slot = ks * 2 + (lane >> 4);
                uint32_t off = (uint32_t)(r * 64 + 16 * (slot ^ ((r >> 1) & 3)));
                ldm_x4(bh[jp], stb + 16384 + off);
                ldm_x4(bl[jp], stb + 24576 + off);
            }
            #pragma unroll
            for (int i2 = 0; i2 < 4; i2++)
                #pragma unroll
                for (int jp = 0; jp < 2; jp++)
                    #pragma unroll
                    for (int sub = 0; sub < 2; sub++) {
                        float* cc = acc[i2][jp * 2 + sub];
                        mma_bf16(cc, ah[i2], bh[jp][sub], bh[jp][sub + 2]);
                        mma_bf16(cc, ah[i2], bl[jp][sub], bl[jp][sub + 2]);
                        mma_bf16(cc, al[i2], bh[jp][sub], bh[jp][sub + 2]);
                    }
        }
    }

    // epilogue: direct stores + bias
    const int row_l = lane >> 2, colq = (lane & 3) * 2;
    #pragma unroll
    for (int i2 = 0; i2 < 4; i2++) {
        int r0 = bm + mi + i2 * 16 + row_l;
        #pragma unroll
        for (int j = 0; j < 4; j++) {
            int cn = bn + ni + j * 8 + colq;
            float b0 = bias[cn], b1 = bias[cn + 1];
            float* cc = acc[i2][j];
            *(float2*)&C[(size_t)r0 * N + cn]       = make_float2(cc[0] + b0, cc[1] + b1);
            *(float2*)&C[(size_t)(r0 + 8) * N + cn] = make_float2(cc[2] + b0, cc[3] + b1);
        }
    }
}

// ---------------------------------------------------------------------------
// YaRN RoPE in-place on Q (heads 0..31) and K (heads 32..39) in g_qkv.
// ---------------------------------------------------------------------------
__global__ void rope_kernel(const int* __restrict__ pos_ids)
{
    const int i  = blockIdx.x;
    const int hh = blockIdx.y;
    const int k  = threadIdx.x;

    float freq = powf(10000.0f, -((float)(2 * k) / 64.0f));
    float wl   = 6.283185307179586f / freq;
    float t    = (wl - 128.0f) / (4096.0f - 128.0f);
    t = fminf(fmaxf(t, 0.0f), 1.0f);
    float eff  = freq * (1.0f - t) + (freq * 0.5f) * t;
    float conc = 0.1f * logf(2.0f) + 1.0f;
    float ang  = (float)pos_ids[i] * eff * conc;
    float sv = sinf(ang), cv = cosf(ang);

    float* p = g_qkv + (size_t)i * QKV_N + hh * DH;
    float x1 = p[k], x2 = p[k + 32];
    p[k]      = x1 * cv - x2 * sv;
    p[k + 32] = x2 * cv + x1 * sv;
}

// ---------------------------------------------------------------------------
// Windowed attention with sink. One block = (query i, kv-group g), computes
// all 4 q-heads of the group off one K/V staging (4x traffic reduction).
// ---------------------------------------------------------------------------
__global__ __launch_bounds__(128)
void attn_kernel(const float* __restrict__ sinks)
{
    const int i   = blockIdx.x;
    const int g   = blockIdx.y;
    const int tid = threadIdx.x;
    const int w   = tid >> 5, l = tid & 31;

    __shared__ float qs[4 * 64];
    __shared__ float Ks[128 * 65];
    __shared__ float ps[4 * 132];
    __shared__ float mh[4], ih[4];
    __shared__ float cp4[128][4];

    const int jstart = max(0, i - (SW_ - 1));
    const int nk     = i - jstart + 1;

    for (int e = tid; e < 256; e += 128) {
        int h = e >> 6, d = e & 63;
        qs[e] = g_qkv[(size_t)i * QKV_N + (g * 4 + h) * DH + d];
    }
    const int kofs = (NH + g) * DH;
    for (int e = tid; e < nk * 64; e += 128) {
        int j = e >> 6, d = e & 63;
        Ks[j * 65 + d] = g_qkv[(size_t)(jstart + j) * QKV_N + kofs + d];
    }
    __syncthreads();

    // scores: thread tid = key j, all 4 heads
    float s[4] = {-INFINITY, -INFINITY, -INFINITY, -INFINITY};
    if (tid < nk) {
        float a0 = 0.f, a1 = 0.f, a2 = 0.f, a3 = 0.f;
        #pragma unroll
        for (int d = 0; d < 64; d++) {
            float kv = Ks[tid * 65 + d];
            a0 += qs[d] * kv; a1 += qs[64 + d] * kv;
            a2 += qs[128 + d] * kv; a3 += qs[192 + d] * kv;
        }
        s[0] = a0 * 0.125f; s[1] = a1 * 0.125f;
        s[2] = a2 * 0.125f; s[3] = a3 * 0.125f;
    }
    #pragma unroll
    for (int h = 0; h < 4; h++) ps[h * 132 + tid] = s[h];
    __syncthreads();

    // warp w reduces max of head w
    {
        float m = fmaxf(fmaxf(ps[w * 132 + l], ps[w * 132 + l + 32]),
                        fmaxf(ps[w * 132 + l + 64], ps[w * 132 + l + 96]));
        #pragma unroll
        for (int off = 16; off > 0; off >>= 1)
            m = fmaxf(m, __shfl_xor_sync(0xffffffffu, m, off));
        if (l == 0) mh[w] = fmaxf(m, sinks[g * 4 + w]);
    }
    __syncthreads();

    #pragma unroll
    for (int h = 0; h < 4; h++) {
        float p = (tid < nk) ? __expf(s[h] - mh[h]) : 0.f;
        ps[h * 132 + tid] = p;
    }
    __syncthreads();

    // warp w reduces sum of head w
    {
        float sm = ps[w * 132 + l] + ps[w * 132 + l + 32] +
                   ps[w * 132 + l + 64] + ps[w * 132 + l + 96];
        #pragma unroll
        for (int off = 16; off > 0; off >>= 1)
            sm += __shfl_xor_sync(0xffffffffu, sm, off);
        if (l == 0) ih[w] = 1.f / (sm + __expf(sinks[g * 4 + w] - mh[w]));
    }

    // stage V (reuse Ks)
    const int vofs = (NH + NG + g) * DH;
    for (int e = tid; e < nk * 64; e += 128) {
        int j = e >> 6, d = e & 63;
        Ks[j * 65 + d] = g_qkv[(size_t)(jstart + j) * QKV_N + vofs + d];
    }
    __syncthreads();

    const int d    = tid & 63;
    const int half = tid >> 6;
    float acc[4] = {0.f, 0.f, 0.f, 0.f};
    for (int j = half; j < nk; j += 2) {
        float v = Ks[j * 65 + d];
        #pragma unroll
        for (int h = 0; h < 4; h++) acc[h] += ps[h * 132 + j] * v;
    }
    #pragma unroll
    for (int h = 0; h < 4; h++) cp4[tid][h] = acc[h];
    __syncthreads();
    if (tid < 64) {
        #pragma unroll
        for (int h = 0; h < 4; h++) {
            float v = (cp4[tid][h] + cp4[64 + tid][h]) * ih[h];
            g_ctx[(size_t)i * E_ + (g * 4 + h) * DH + tid] = v;
        }
    }
}

// ---------------------------------------------------------------------------
extern "C" void kernel_launch(void* const* d_in, const int* in_sizes, int n_in,
                              void* d_out, int out_size)
{
    const float* x     = (const float*)d_in[0];
    const int*   pos   = (const int*)  d_in[1];
    const float* Wqkv  = (const float*)d_in[3];
    const float* bqkv  = (const float*)d_in[4];
    const float* Wout  = (const float*)d_in[5];
    const float* bout  = (const float*)d_in[6];
    const float* sinks = (const float*)d_in[7];
    float* out = (float*)d_out;

    float *qkv_p = nullptr, *ctx_p = nullptr;
    __nv_bfloat16 *xhi, *xlo, *wqhi, *wqlo, *wohi, *wolo, *chi, *clo;
    cudaGetSymbolAddress((void**)&qkv_p, g_qkv);
    cudaGetSymbolAddress((void**)&ctx_p, g_ctx);
    cudaGetSymbolAddress((void**)&xhi,  g_xhi);  cudaGetSymbolAddress((void**)&xlo,  g_xlo);
    cudaGetSymbolAddress((void**)&wqhi, g_wqhi); cudaGetSymbolAddress((void**)&wqlo, g_wqlo);
    cudaGetSymbolAddress((void**)&wohi, g_wohi); cudaGetSymbolAddress((void**)&wolo, g_wolo);
    cudaGetSymbolAddress((void**)&chi,  g_chi);  cudaGetSymbolAddress((void**)&clo,  g_clo);

    cudaFuncSetAttribute(gemm_mma, cudaFuncAttributeMaxDynamicSharedMemorySize, GEMM_SMEM);

    // 0) split inputs into bf16 hi/lo
    {
        int n4 = (S_ * E_) / 4;
        conv_hilo<<<(n4 + 255) / 256, 256>>>(x, xhi, xlo, n4);
        n4 = (QKV_N * E_) / 4;
        conv_hilo<<<(n4 + 255) / 256, 256>>>(Wqkv, wqhi, wqlo, n4);
        n4 = (E_ * E_) / 4;
        conv_hilo<<<(n4 + 255) / 256, 256>>>(Wout, wohi, wolo, n4);
    }

    // 1) qkv = x @ Wqkv^T + bqkv
    gemm_mma<<<dim3(QKV_N / 128, S_ / 128), 256, GEMM_SMEM>>>(
        S_, QKV_N, E_, xhi, xlo, wqhi, wqlo, bqkv, qkv_p);

    // 2) RoPE
    rope_kernel<<<dim3(S_, NH + NG), 32>>>(pos);

    // 3) windowed sink attention (grouped)
    attn_kernel<<<dim3(S_, NG), 128>>>(sinks);

    // 4) ctx -> bf16 hi/lo, then out = ctx @ Wout^T + bout
    {
        int n4 = (S_ * E_) / 4;
        conv_hilo<<<(n4 + 255) / 256, 256>>>(ctx_p, chi, clo, n4);
    }
    gemm_mma<<<dim3(E_ / 128, S_ / 128), 256, GEMM_SMEM>>>(
        S_, E_, E_, chi, clo, wohi, wolo, bout, out);
}